// round 15
// baseline (speedup 1.0000x reference)
#include <cuda_runtime.h>

// LSTM forward, GB300 sm_103a, fp32 with packed fma.rn.f32x2 (FFMA2).
//
// R14: R12's cross-CTA split-K regressed (34.4us vs 31.0us; issue 26%, L1 60%)
// => step kernel is smem-WAVEFRONT bound, not occupancy bound. This version
// halves LDS wavefronts per FFMA2: thread tile = 8 cols x 2 batch with f32x2
// packing over COL-PAIRS (w loads are pack-free via float4 reinterpret);
// per warp-k: 3 wavefronts for 8 FFMA2 (was 3 for 4). K split 2-way INSIDE
// the CTA (2 groups x 128 threads, partials combined via smem — no global
// sync). Weights repacked [colblock][k][32] for contiguous per-CTA streams.

#define BATCH 64
#define TT    512
#define EMBD  512
#define HID   1024
#define G4    4096
#define KTILE 32
#define NTILE 16      // tiles per K-half: 512/32

typedef unsigned long long ull;

// ---------------- device scratch (static only — harness rule) --------------
__device__ float g_Wxp[EMBD * G4];                 //  8 MB packed Wx  [k][c]
__device__ float g_Whp2[128 * HID * 32];           // 16 MB packed Wh  [cb][k][cc]
__device__ float g_bp[G4];
__device__ float g_GX[(size_t)TT * G4 * BATCH];    // 512 MB gates_x (+bias) [t][c][b]
__device__ float g_H0[HID * BATCH];                // hT ping  [k][b]
__device__ float g_H1[HID * BATCH];                // hT pong
__device__ float g_C [HID * BATCH];                // cT

// ---------------- packed fp32x2 helpers ------------------------------------
__device__ __forceinline__ ull ffma2(ull a, ull b, ull c) {
    ull d;
    asm("fma.rn.f32x2 %0, %1, %2, %3;" : "=l"(d) : "l"(a), "l"(b), "l"(c));
    return d;
}
__device__ __forceinline__ ull add2(ull a, ull b) {
    ull d;
    asm("add.rn.f32x2 %0, %1, %2;" : "=l"(d) : "l"(a), "l"(b));
    return d;
}
__device__ __forceinline__ ull pack2(float x, float y) {
    ull r;
    asm("mov.b64 %0, {%1, %2};" : "=l"(r) : "f"(x), "f"(y));
    return r;
}
__device__ __forceinline__ float2 unpack2(ull v) {
    float2 f;
    asm("mov.b64 {%0, %1}, %2;" : "=f"(f.x), "=f"(f.y) : "l"(v));
    return f;
}
__device__ __forceinline__ float sigmoidf_(float x) {
    return 1.0f / (1.0f + __expf(-x));
}

// ---------------- 1. zero state (graph-replay idempotence) -----------------
__global__ void zero_state() {
    int i = blockIdx.x * blockDim.x + threadIdx.x;
    if (i < HID * BATCH) { g_H0[i] = 0.0f; g_C[i] = 0.0f; }
}

// ---------------- 2. pack weights ------------------------------------------
// Wx: [k][c] with c = h*4+g.   Wh: [cb][k][cc] with c = cb*32+cc = h*4+g.
__global__ void pack_weights(const float* Wxi, const float* Wxf, const float* Wxc, const float* Wxo,
                             const float* Whi, const float* Whf, const float* Whc, const float* Who,
                             const float* bi,  const float* bf,  const float* bc,  const float* bo) {
    const float* Wx[4] = {Wxi, Wxf, Wxc, Wxo};
    const float* Wh[4] = {Whi, Whf, Whc, Who};
    const float* bb[4] = {bi, bf, bc, bo};
    int stride = gridDim.x * blockDim.x;
    int tid0   = blockIdx.x * blockDim.x + threadIdx.x;
    for (int idx = tid0; idx < 4 * HID * HID; idx += stride) {
        int g = idx >> 20, r = idx & ((1 << 20) - 1);
        int k = r >> 10, h = r & 1023;
        int c = (h << 2) + g;
        g_Whp2[(size_t)(c >> 5) * (HID * 32) + k * 32 + (c & 31)] = Wh[g][r];
    }
    for (int idx = tid0; idx < 4 * EMBD * HID; idx += stride) {
        int g = idx >> 19, r = idx & ((1 << 19) - 1);
        int e = r >> 10, h = r & 1023;
        g_Wxp[e * G4 + (h << 2) + g] = Wx[g][r];
    }
    for (int idx = tid0; idx < G4; idx += stride) {
        int g = idx >> 10, h = idx & 1023;
        g_bp[(h << 2) + g] = bb[g][h];
    }
}

// ---------------- 3. phase-1 GEMM: GX = xe @ Wxp + b (unchanged) -----------
#define P1_BM 128
#define P1_BN 64
#define P1_BK 32
__global__ void __launch_bounds__(256) phase1_gemm(const int* xx, const float* emb) {
    __shared__ __align__(16) float As[P1_BK][P1_BM + 4];
    __shared__ __align__(16) float Bs[P1_BK][P1_BN];
    __shared__ const float* rowp[P1_BM];

    int tid = threadIdx.x;
    int r0  = blockIdx.y * P1_BM;
    int c0  = blockIdx.x * P1_BN;

    if (tid < P1_BM) {
        int r = r0 + tid;
        int t = r >> 6, b = r & 63;
        rowp[tid] = emb + (size_t)xx[b * TT + t] * EMBD;
    }
    __syncthreads();

    int tx = tid & 15, ty = tid >> 4;
    ull acc[4][4];
    #pragma unroll
    for (int p = 0; p < 4; p++)
        #pragma unroll
        for (int j = 0; j < 4; j++) acc[p][j] = 0ull;

    int lm = tid >> 1, lh = (tid & 1) * 16;
    int bk = tid >> 3, bc = (tid & 7) * 4;

    for (int k0 = 0; k0 < EMBD; k0 += P1_BK) {
        float4 av[4];
        const float* rp = rowp[lm] + k0 + lh;
        #pragma unroll
        for (int i = 0; i < 4; i++) av[i] = *(const float4*)(rp + 4 * i);
        float4 bv0 = *(const float4*)(g_Wxp + (size_t)(k0 + bk) * G4 + c0 + bc);
        float4 bv1 = *(const float4*)(g_Wxp + (size_t)(k0 + bk) * G4 + c0 + bc + 32);

        __syncthreads();
        #pragma unroll
        for (int i = 0; i < 4; i++) {
            As[lh + 4 * i + 0][lm] = av[i].x;
            As[lh + 4 * i + 1][lm] = av[i].y;
            As[lh + 4 * i + 2][lm] = av[i].z;
            As[lh + 4 * i + 3][lm] = av[i].w;
        }
        *(float4*)&Bs[bk][bc]      = bv0;
        *(float4*)&Bs[bk][bc + 32] = bv1;
        __syncthreads();

        #pragma unroll
        for (int k = 0; k < P1_BK; k++) {
            ulonglong2 a01 = *(const ulonglong2*)&As[k][ty * 8];
            ulonglong2 a23 = *(const ulonglong2*)&As[k][ty * 8 + 4];
            float4 b4 = *(const float4*)&Bs[k][tx * 4];
            ull aav[4] = {a01.x, a01.y, a23.x, a23.y};
            ull bbv[4] = {pack2(b4.x, b4.x), pack2(b4.y, b4.y),
                          pack2(b4.z, b4.z), pack2(b4.w, b4.w)};
            #pragma unroll
            for (int p = 0; p < 4; p++)
                #pragma unroll
                for (int j = 0; j < 4; j++)
                    acc[p][j] = ffma2(aav[p], bbv[j], acc[p][j]);
        }
    }

    float bpv[4];
    #pragma unroll
    for (int j = 0; j < 4; j++) bpv[j] = g_bp[c0 + tx * 4 + j];
    #pragma unroll
    for (int p = 0; p < 4; p++) {
        int m = ty * 8 + 2 * p;
        int r = r0 + m;
        int t = r >> 6, b = r & 63;
        float* base = g_GX + (size_t)t * (G4 * BATCH) + (size_t)(c0 + tx * 4) * BATCH + b;
        #pragma unroll
        for (int j = 0; j < 4; j++) {
            float2 v = unpack2(acc[p][j]);
            v.x += bpv[j]; v.y += bpv[j];
            *(float2*)(base + j * BATCH) = v;
        }
    }
}

// ---------------- 4. one LSTM step -----------------------------------------
// grid 128 (CTA cb = 32 packed cols = 8 h-units), block 256 = 2 K-groups x 128.
// Group kg reduces k in [kg*512, kg*512+512). Thread (tx=col-oct 0..3,
// ty=b-pair 0..31): 8 cols x 2 b = 8 f32x2 accs packed over col-pairs.
// Per warp per k: 1 LDS.64 (a) + 2 LDS.128 (w) = 3 wavefronts, 8 FFMA2.
__global__ void __launch_bounds__(256, 1) lstm_step(int t) {
    __shared__ __align__(16) float sh_h[2][2][KTILE * 64];   // 32 KB [grp][buf][k][b]
    __shared__ __align__(16) float sh_w[2][2][KTILE * 32];   // 16 KB [grp][buf][k][cc]

    int tid = threadIdx.x;
    int kg  = tid >> 7;            // K-group 0/1
    int t7  = tid & 127;
    int tx8 = (t7 & 3) * 8;        // first of 8 cols
    int ty  = t7 >> 2;             // b-pair 0..31
    int ty2 = ty * 2;
    int cb  = blockIdx.x;
    int c0  = cb * 32;
    int h0  = cb * 8;

    const float* hin  = (t & 1) ? g_H1 : g_H0;
    float*       hout = (t & 1) ? g_H0 : g_H1;

    // acc[cp][jb]: f32x2 over (col tx8+2cp, tx8+2cp+1) at batch ty2+jb
    ull acc[4][2];
    if (kg == 0) {   // group 0 carries gx+bias
        const float* gxb = g_GX + (size_t)t * (G4 * BATCH) + (size_t)c0 * BATCH;
        #pragma unroll
        for (int cp = 0; cp < 4; cp++)
            #pragma unroll
            for (int jb = 0; jb < 2; jb++) {
                const float* p = gxb + (tx8 + 2 * cp) * BATCH + ty2 + jb;
                acc[cp][jb] = pack2(p[0], p[BATCH]);
            }
    } else {
        #pragma unroll
        for (int cp = 0; cp < 4; cp++)
            #pragma unroll
            for (int jb = 0; jb < 2; jb++) acc[cp][jb] = 0ull;
    }

    const float* hsrc0 = hin + (kg * 512) * 64;
    const float* wsrc0 = g_Whp2 + (size_t)cb * (HID * 32) + (kg * 512) * 32;

    float4 hr[4], wr[2];
    // preload tile 0
    #pragma unroll
    for (int j = 0; j < 4; j++) hr[j] = *(const float4*)(hsrc0 + t7 * 16 + 4 * j);
    #pragma unroll
    for (int j = 0; j < 2; j++) wr[j] = *(const float4*)(wsrc0 + t7 * 8 + 4 * j);
    #pragma unroll
    for (int j = 0; j < 4; j++) *(float4*)(&sh_h[kg][0][0] + t7 * 16 + 4 * j) = hr[j];
    #pragma unroll
    for (int j = 0; j < 2; j++) *(float4*)(&sh_w[kg][0][0] + t7 * 8 + 4 * j) = wr[j];
    __syncthreads();

    int cur = 0;
    for (int tile = 0; tile < NTILE; ++tile) {
        if (tile < NTILE - 1) {   // register prefetch of next tile
            const float* hs = hsrc0 + (tile + 1) * (KTILE * 64);
            const float* ws = wsrc0 + (tile + 1) * (KTILE * 32);
            #pragma unroll
            for (int j = 0; j < 4; j++) hr[j] = *(const float4*)(hs + t7 * 16 + 4 * j);
            #pragma unroll
            for (int j = 0; j < 2; j++) wr[j] = *(const float4*)(ws + t7 * 8 + 4 * j);
        }
        const float* hb = &sh_h[kg][cur][0];
        const float* wb = &sh_w[kg][cur][0];
        #pragma unroll
        for (int k = 0; k < KTILE; k++) {
            float2 a2 = *(const float2*)(hb + k * 64 + ty2);          // 1 wf (64B)
            ulonglong2 w01 = *(const ulonglong2*)(wb + k * 32 + tx8);     // 1 wf
            ulonglong2 w23 = *(const ulonglong2*)(wb + k * 32 + tx8 + 4); // 1 wf
            ull pa0 = pack2(a2.x, a2.x);
            ull pa1 = pack2(a2.y, a2.y);
            acc[0][0] = ffma2(w01.x, pa0, acc[0][0]);
            acc[0][1] = ffma2(w01.x, pa1, acc[0][1]);
            acc[1][0] = ffma2(w01.y, pa0, acc[1][0]);
            acc[1][1] = ffma2(w01.y, pa1, acc[1][1]);
            acc[2][0] = ffma2(w23.x, pa0, acc[2][0]);
            acc[2][1] = ffma2(w23.x, pa1, acc[2][1]);
            acc[3][0] = ffma2(w23.y, pa0, acc[3][0]);
            acc[3][1] = ffma2(w23.y, pa1, acc[3][1]);
        }
        if (tile < NTILE - 1) {
            int nxt = cur ^ 1;
            #pragma unroll
            for (int j = 0; j < 4; j++) *(float4*)(&sh_h[kg][nxt][0] + t7 * 16 + 4 * j) = hr[j];
            #pragma unroll
            for (int j = 0; j < 2; j++) *(float4*)(&sh_w[kg][nxt][0] + t7 * 8 + 4 * j) = wr[j];
            __syncthreads();
            cur = nxt;
        }
    }

    // ---- combine group 1 partials into group 0 (via smem, aliased) ----
    ull*   Ps = (ull*)&sh_w[0][0][0];         // 1024 ull = 8 KB
    float* Gs = (float*)&sh_h[0][0][0];       // 32 x 64 floats = 8 KB

    __syncthreads();                          // all compute done (buffers free)
    if (kg == 1) {
        #pragma unroll
        for (int cp = 0; cp < 4; cp++)
            #pragma unroll
            for (int jb = 0; jb < 2; jb++)
                Ps[(((t7 & 3) * 4 + cp) * 32 + ty) * 2 + jb] = acc[cp][jb];
    }
    __syncthreads();
    if (kg == 0) {
        #pragma unroll
        for (int cp = 0; cp < 4; cp++)
            #pragma unroll
            for (int jb = 0; jb < 2; jb++) {
                ull s = add2(acc[cp][jb], Ps[(((t7 & 3) * 4 + cp) * 32 + ty) * 2 + jb]);
                float2 v = unpack2(s);
                Gs[(tx8 + 2 * cp) * 64 + ty2 + jb]     = v.x;
                Gs[(tx8 + 2 * cp + 1) * 64 + ty2 + jb] = v.y;
            }
    }
    __syncthreads();

    // ---- elementwise LSTM cell (all 256 threads, 512 outputs) ----
    for (int ii = tid; ii < 512; ii += 256) {
        int hh = ii >> 6, b = ii & 63;
        float gi = Gs[(hh * 4 + 0) * 64 + b];
        float gf = Gs[(hh * 4 + 1) * 64 + b];
        float gc = Gs[(hh * 4 + 2) * 64 + b];
        float go = Gs[(hh * 4 + 3) * 64 + b];
        float iv = sigmoidf_(gi);
        float fv = sigmoidf_(gf);
        float gv = tanhf(gc);
        float ov = sigmoidf_(go);
        int off = (h0 + hh) * 64 + b;
        float c = fv * g_C[off] + iv * gv;
        g_C[off]  = c;
        hout[off] = ov * tanhf(c);
    }
}

// ---------------- 5. output projection: out = h @ Why + by -----------------
__global__ void out_kernel(const float* Why, const float* by, float* out) {
    __shared__ float red[256];
    int b = blockIdx.x >> 1, o = blockIdx.x & 1;
    float s = 0.0f;
    for (int k = threadIdx.x; k < HID; k += 256)
        s += g_H0[k * 64 + b] * Why[k * 2 + o];   // T=512 even -> final h in g_H0
    red[threadIdx.x] = s;
    __syncthreads();
    for (int st = 128; st > 0; st >>= 1) {
        if (threadIdx.x < st) red[threadIdx.x] += red[threadIdx.x + st];
        __syncthreads();
    }
    if (threadIdx.x == 0) out[b * 2 + o] = red[0] + by[o];
}

// ---------------- launch ----------------------------------------------------
extern "C" void kernel_launch(void* const* d_in, const int* in_sizes, int n_in,
                              void* d_out, int out_size) {
    const int*   x   = (const int*)  d_in[0];
    const float* emb = (const float*)d_in[1];
    const float* Wxi = (const float*)d_in[2];
    const float* Whi = (const float*)d_in[3];
    const float* bi  = (const float*)d_in[4];
    const float* Wxf = (const float*)d_in[5];
    const float* Whf = (const float*)d_in[6];
    const float* bf  = (const float*)d_in[7];
    const float* Wxc = (const float*)d_in[8];
    const float* Whc = (const float*)d_in[9];
    const float* bc  = (const float*)d_in[10];
    const float* Wxo = (const float*)d_in[11];
    const float* Who = (const float*)d_in[12];
    const float* bo  = (const float*)d_in[13];
    const float* Why = (const float*)d_in[14];
    const float* by  = (const float*)d_in[15];
    float* out = (float*)d_out;

    zero_state<<<256, 256>>>();
    pack_weights<<<2048, 256>>>(Wxi, Wxf, Wxc, Wxo, Whi, Whf, Whc, Who, bi, bf, bc, bo);

    dim3 g1(G4 / P1_BN, (TT * BATCH) / P1_BM);   // (64, 256)
    phase1_gemm<<<g1, 256>>>(x, emb);

    for (int t = 0; t < TT; ++t)
        lstm_step<<<128, 256>>>(t);

    out_kernel<<<128, 256>>>(Why, by, out);
}